// round 5
// baseline (speedup 1.0000x reference)
#include <cuda_runtime.h>
#include <cuda_bf16.h>
#include <cstdint>

// SpectralInverse, fully tensorized:
//   Y  = pos * w^T + b      -> bf16 split m16n8k8 MMA (2 passes), D-frag == next A-frag layout
//   C  = cos(Y)             -> MUFU, straight into A fragments
//   U  = C * h_bf16         -> m16n8k16 MMA, fp32 accum
//   out= u_b + (u_w/N) * U  -> m16n8k16 MMA (sin(x)~x at |x|<4e-4)

#define BATCH 4
#define NF 128
#define CIN 64
#define COUT 8
#define NGRID (48*48*48)
#define TPB 512
#define PTS_PER_CTA 512
#define CTAS_PER_BATCH (NGRID / PTS_PER_CTA)   // 216
#define TWO_PI_F 6.28318530717958647692f

#define BSTRIDE 72      // main-B (h) padded row stride in u32
#define WBSTRIDE 136    // Y-B row stride in u32 (8t+g bank pattern -> conflict-free)

__device__ __forceinline__ uint32_t pack_bf16x2(float lo, float hi) {
    uint32_t r;
    asm("cvt.rn.bf16x2.f32 %0, %1, %2;" : "=r"(r) : "f"(hi), "f"(lo));
    return r;  // r[15:0]=bf16(lo), r[31:16]=bf16(hi)
}
__device__ __forceinline__ float bf16rt(float x) {   // round-trip through bf16
    return __bfloat162float(__float2bfloat16(x));
}

__device__ __forceinline__ void mma16816(float* d,
                                          uint32_t a0, uint32_t a1, uint32_t a2, uint32_t a3,
                                          uint32_t b0, uint32_t b1) {
    asm volatile("mma.sync.aligned.m16n8k16.row.col.f32.bf16.bf16.f32 "
                 "{%0,%1,%2,%3}, {%4,%5,%6,%7}, {%8,%9}, {%0,%1,%2,%3};"
                 : "+f"(d[0]), "+f"(d[1]), "+f"(d[2]), "+f"(d[3])
                 : "r"(a0), "r"(a1), "r"(a2), "r"(a3), "r"(b0), "r"(b1));
}
// m16n8k8, D = A*B + 0  (fresh accumulator)
__device__ __forceinline__ void mma1688_z(float* d, uint32_t a0, uint32_t a1, uint32_t b) {
    asm volatile("mma.sync.aligned.m16n8k8.row.col.f32.bf16.bf16.f32 "
                 "{%0,%1,%2,%3}, {%4,%5}, {%6}, {%7,%7,%7,%7};"
                 : "=f"(d[0]), "=f"(d[1]), "=f"(d[2]), "=f"(d[3])
                 : "r"(a0), "r"(a1), "r"(b), "f"(0.0f));
}
// m16n8k8, D += A*B
__device__ __forceinline__ void mma1688_a(float* d, uint32_t a0, uint32_t a1, uint32_t b) {
    asm volatile("mma.sync.aligned.m16n8k8.row.col.f32.bf16.bf16.f32 "
                 "{%0,%1,%2,%3}, {%4,%5}, {%6}, {%0,%1,%2,%3};"
                 : "+f"(d[0]), "+f"(d[1]), "+f"(d[2]), "+f"(d[3])
                 : "r"(a0), "r"(a1), "r"(b));
}

// Position A-fragment word for k-slots (2t, 2t+1): [x_h,y_h,z_h,1, x_m,y_m,z_m,1]
__device__ __forceinline__ uint32_t apos(float4 q, int t) {
    float xh = bf16rt(q.x), yh = bf16rt(q.y), zh = bf16rt(q.z);
    if (t == 0) return pack_bf16x2(xh, yh);
    if (t == 1) return pack_bf16x2(zh, 1.0f);
    if (t == 2) return pack_bf16x2(q.x - xh, q.y - yh);
    return pack_bf16x2(q.z - zh, 1.0f);
}

__global__ void __launch_bounds__(TPB, 1)
spectral_hmma3_kernel(const float* __restrict__ h,
                      const float* __restrict__ y,
                      const float* __restrict__ y_w,
                      const float* __restrict__ y_b,
                      const float* __restrict__ u_w,
                      const float* __restrict__ u_b,
                      float* __restrict__ out)
{
    __shared__ uint32_t s_bhi[64 * BSTRIDE];      // 18432 B  (h bf16, k-pair packed)
    __shared__ float4   s_pts[PTS_PER_CTA];       // 8192 B
    __shared__ uint32_t s_wb[2 * 4 * WBSTRIDE];   // 4352 B  (Y-MMA B fragments, 2 passes)
    __shared__ uint32_t s_uwp[COUT * 40];         // 1280 B
    __shared__ float    s_ub[COUT];

    const int tid  = threadIdx.x;
    const int bIdx = blockIdx.x / CTAS_PER_BATCH;
    const int blk  = blockIdx.x % CTAS_PER_BATCH;

    // ---------------- staging ----------------
    {   // h -> bf16, k-pair packed word[f/2][m]
        const float* hb = h + (size_t)bIdx * NF * CIN;
        __nv_bfloat16* bh = (__nv_bfloat16*)s_bhi;
        #pragma unroll
        for (int it = 0; it < (NF * CIN) / TPB; it++) {
            int i = tid + it * TPB;
            int f = i >> 6, m = i & 63;
            bh[((f >> 1) * BSTRIDE + m) * 2 + (f & 1)] = __float2bfloat16(hb[i]);
        }
    }
    {   // Y-MMA B fragments: 2 passes x 4 k-pairs x 128 f
        // pass1 rows k: [wx_h,wy_h,wz_h,b_h, wx_h,wy_h,wz_h,b_m]
        // pass2 rows k: [wx_m,wy_m,wz_m,0,   wx_m,wy_m,wz_m,0 ]
        const int f = tid & 127;
        const int sec = tid >> 7;                 // 0..3 -> entries e = 2*sec, 2*sec+1
        float wx = TWO_PI_F * y_w[f * 3], wy = TWO_PI_F * y_w[f * 3 + 1], wz = TWO_PI_F * y_w[f * 3 + 2];
        float bb = TWO_PI_F * y_b[f];
        float wxh = bf16rt(wx), wyh = bf16rt(wy), wzh = bf16rt(wz), bh_ = bf16rt(bb);
        float wxm = wx - wxh, wym = wy - wyh, wzm = wz - wzh, bm_ = bb - bh_;
        #pragma unroll
        for (int ee = 0; ee < 2; ee++) {
            int e = sec * 2 + ee;
            int pass = e >> 2, j = e & 3;
            float lo, hi;
            if (pass == 0) {
                if (j == 0 || j == 2) { lo = wxh; hi = wyh; }
                else if (j == 1)      { lo = wzh; hi = bh_; }
                else                  { lo = wzh; hi = bm_; }
            } else {
                if (j == 0 || j == 2) { lo = wxm; hi = wym; }
                else                  { lo = wzm; hi = 0.0f; }
            }
            s_wb[pass * (4 * WBSTRIDE) + j * WBSTRIDE + f] = pack_bf16x2(lo, hi);
        }
    }
    {   // grid positions, padded to float4
        const float* yg = y + ((size_t)bIdx * NGRID + (size_t)blk * PTS_PER_CTA) * 3;
        float* sp = (float*)s_pts;
        #pragma unroll
        for (int it = 0; it < (PTS_PER_CTA * 4) / TPB; it++) {
            int j = tid + it * TPB;
            int pt = j >> 2, c = j & 3;
            sp[j] = (c < 3) ? yg[pt * 3 + c] : 0.0f;
        }
    }
    if (tid < (COUT * CIN) / 2) {
        int o = tid >> 5, j = tid & 31;
        const float inv_n = 1.0f / (float)NGRID;
        s_uwp[o * 40 + j] = pack_bf16x2(u_w[o * CIN + 2 * j] * inv_n,
                                        u_w[o * CIN + 2 * j + 1] * inv_n);
    }
    if (tid < COUT) s_ub[tid] = u_b[tid];
    __syncthreads();

    // ---------------- per-warp setup: M=32 rows ----------------
    const int warp = tid >> 5;
    const int lane = tid & 31;
    const int g  = lane >> 2;
    const int t  = lane & 3;
    const int base = warp * 32;

    // Position A-fragments (constant across kt): m-tile0 rows g/g+8, m-tile1 rows g+16/g+24
    const uint32_t aP00 = apos(s_pts[base + g],      t);
    const uint32_t aP01 = apos(s_pts[base + g + 8],  t);
    const uint32_t aP10 = apos(s_pts[base + g + 16], t);
    const uint32_t aP11 = apos(s_pts[base + g + 24], t);

    float acc0[8][4], acc1[8][4];
    #pragma unroll
    for (int nt = 0; nt < 8; nt++)
        #pragma unroll
        for (int j = 0; j < 4; j++) { acc0[nt][j] = 0.f; acc1[nt][j] = 0.f; }

    const uint32_t* bh0 = s_bhi + t * BSTRIDE + g;
    const uint32_t* wb0 = s_wb + t * WBSTRIDE + g;

    #pragma unroll
    for (int kt = 0; kt < 8; kt++) {
        // ---- Y via split MMA, then cos into main A-fragments ----
        uint32_t a0, a1, a2, a3, a4, a5, a6, a7;
        #pragma unroll
        for (int nt2 = 0; nt2 < 2; nt2++) {
            const uint32_t col = kt * 16 + nt2 * 8;
            uint32_t b1 = wb0[col];                      // pass1 B frag
            uint32_t b2 = wb0[4 * WBSTRIDE + col];       // pass2 B frag
            float d0[4], d1[4];
            mma1688_z(d0, aP00, aP01, b1);
            mma1688_a(d0, aP00, aP01, b2);
            mma1688_z(d1, aP10, aP11, b1);
            mma1688_a(d1, aP10, aP11, b2);
            uint32_t f0 = pack_bf16x2(__cosf(d0[0]), __cosf(d0[1]));
            uint32_t f1 = pack_bf16x2(__cosf(d0[2]), __cosf(d0[3]));
            uint32_t f2 = pack_bf16x2(__cosf(d1[0]), __cosf(d1[1]));
            uint32_t f3 = pack_bf16x2(__cosf(d1[2]), __cosf(d1[3]));
            if (nt2 == 0) { a0 = f0; a1 = f1; a4 = f2; a5 = f3; }
            else          { a2 = f0; a3 = f1; a6 = f2; a7 = f3; }
        }
        // ---- main GEMM: C * h ----
        const uint32_t* bh = bh0 + kt * (8 * BSTRIDE);
        #pragma unroll
        for (int nt = 0; nt < 8; nt++) {
            uint32_t b0 = bh[nt * 8];
            uint32_t b1 = bh[nt * 8 + 4 * BSTRIDE];
            mma16816(acc0[nt], a0, a1, a2, a3, b0, b1);
            mma16816(acc1[nt], a4, a5, a6, a7, b0, b1);
        }
    }

    // ---------------- epilogue: out = u_b + (u_w/N) * U ----------------
    const float ub0 = s_ub[2 * t], ub1 = s_ub[2 * t + 1];
    float e0[4] = {ub0, ub1, ub0, ub1};
    float e1[4] = {ub0, ub1, ub0, ub1};
    #pragma unroll
    for (int kt2 = 0; kt2 < 4; kt2++) {
        uint32_t b0 = s_uwp[g * 40 + 8 * kt2 + t];
        uint32_t b1 = s_uwp[g * 40 + 8 * kt2 + t + 4];
        mma16816(e0,
                 pack_bf16x2(acc0[2 * kt2][0],     acc0[2 * kt2][1]),
                 pack_bf16x2(acc0[2 * kt2][2],     acc0[2 * kt2][3]),
                 pack_bf16x2(acc0[2 * kt2 + 1][0], acc0[2 * kt2 + 1][1]),
                 pack_bf16x2(acc0[2 * kt2 + 1][2], acc0[2 * kt2 + 1][3]),
                 b0, b1);
        mma16816(e1,
                 pack_bf16x2(acc1[2 * kt2][0],     acc1[2 * kt2][1]),
                 pack_bf16x2(acc1[2 * kt2][2],     acc1[2 * kt2][3]),
                 pack_bf16x2(acc1[2 * kt2 + 1][0], acc1[2 * kt2 + 1][1]),
                 pack_bf16x2(acc1[2 * kt2 + 1][2], acc1[2 * kt2 + 1][3]),
                 b0, b1);
    }

    const size_t pt = (size_t)bIdx * NGRID + (size_t)blk * PTS_PER_CTA + base + g;
    *(float2*)(out + (pt +  0) * COUT + 2 * t) = make_float2(e0[0], e0[1]);
    *(float2*)(out + (pt +  8) * COUT + 2 * t) = make_float2(e0[2], e0[3]);
    *(float2*)(out + (pt + 16) * COUT + 2 * t) = make_float2(e1[0], e1[1]);
    *(float2*)(out + (pt + 24) * COUT + 2 * t) = make_float2(e1[2], e1[3]);
}

extern "C" void kernel_launch(void* const* d_in, const int* in_sizes, int n_in,
                              void* d_out, int out_size) {
    const float* h   = (const float*)d_in[0];
    const float* y   = (const float*)d_in[1];
    const float* y_w = (const float*)d_in[2];
    const float* y_b = (const float*)d_in[3];
    const float* u_w = (const float*)d_in[4];
    const float* u_b = (const float*)d_in[5];
    float* out = (float*)d_out;

    dim3 grid(BATCH * CTAS_PER_BATCH);   // 864 CTAs
    spectral_hmma3_kernel<<<grid, TPB>>>(h, y, y_w, y_b, u_w, u_b, out);
}

// round 6
// speedup vs baseline: 1.3731x; 1.3731x over previous
#include <cuda_runtime.h>
#include <cuda_bf16.h>
#include <cstdint>

// SpectralInverse, linearized tail:
//   sin(x) ~ x at |x|<4e-4  =>  out[p,o] = u_b[o] + sum_f cos(2pi*Y[p,f]) * G[f,o]
//   with G = h . u_w^T / Ngrid  (precomputed once per launch, bf16, [4][128][8])
// Main kernel: per-warp M=32 x K=128 x N=8 bf16 HMMA, cos generated straight into A-fragments.

#define BATCH 4
#define NF 128
#define CIN 64
#define COUT 8
#define NGRID (48*48*48)
#define TPB 256
#define PTS_PER_CTA 256
#define CTAS_PER_BATCH (NGRID / PTS_PER_CTA)   // 432
#define TWO_PI_F 6.28318530717958647692f

// G as bf16x2 words: [batch][f/2][o] -> 4*64*8 = 2048 words
__device__ uint32_t g_G[BATCH * 64 * COUT];

__device__ __forceinline__ uint32_t pack_bf16x2(float lo, float hi) {
    uint32_t r;
    asm("cvt.rn.bf16x2.f32 %0, %1, %2;" : "=r"(r) : "f"(hi), "f"(lo));
    return r;  // r[15:0]=bf16(lo), r[31:16]=bf16(hi)
}

__device__ __forceinline__ void mma16816(float* d,
                                          uint32_t a0, uint32_t a1, uint32_t a2, uint32_t a3,
                                          uint32_t b0, uint32_t b1) {
    asm volatile("mma.sync.aligned.m16n8k16.row.col.f32.bf16.bf16.f32 "
                 "{%0,%1,%2,%3}, {%4,%5,%6,%7}, {%8,%9}, {%0,%1,%2,%3};"
                 : "+f"(d[0]), "+f"(d[1]), "+f"(d[2]), "+f"(d[3])
                 : "r"(a0), "r"(a1), "r"(a2), "r"(a3), "r"(b0), "r"(b1));
}

// w pre-scaled by 2*pi; __cosf handles range reduction.
__device__ __forceinline__ float cosv(float4 w, float3 p) {
    return __cosf(fmaf(w.x, p.x, fmaf(w.y, p.y, fmaf(w.z, p.z, w.w))));
}

// ---------------- kernel 1: G = h . u_w^T / N  (bf16 pairs) ----------------
__global__ void precompute_G_kernel(const float* __restrict__ h,
                                    const float* __restrict__ u_w)
{
    const int idx = blockIdx.x * blockDim.x + threadIdx.x;   // 0..2047
    const int b  = idx >> 9;
    const int fp = (idx >> 3) & 63;
    const int o  = idx & 7;
    const float* h0 = h + ((size_t)b * NF + 2 * fp) * CIN;
    const float* uw = u_w + o * CIN;
    float g0 = 0.f, g1 = 0.f;
    #pragma unroll
    for (int m = 0; m < CIN; m++) {
        float u = uw[m];
        g0 = fmaf(h0[m], u, g0);
        g1 = fmaf(h0[CIN + m], u, g1);
    }
    const float inv_n = 1.0f / (float)NGRID;
    g_G[idx] = pack_bf16x2(g0 * inv_n, g1 * inv_n);
}

// ---------------- kernel 2: main ----------------
__global__ void __launch_bounds__(TPB, 3)
spectral_hmma4_kernel(const float* __restrict__ y,
                      const float* __restrict__ y_w,
                      const float* __restrict__ y_b,
                      const float* __restrict__ u_b,
                      float* __restrict__ out)
{
    __shared__ float4   s_pts[PTS_PER_CTA];   // 4096 B
    __shared__ float4   s_yw[NF];             // 2048 B (2pi-scaled w0,w1,w2,b)
    __shared__ uint32_t s_G[64 * COUT];       // 2048 B (this batch's G words)
    __shared__ float    s_ub[COUT];

    const int tid  = threadIdx.x;
    const int bIdx = blockIdx.x / CTAS_PER_BATCH;
    const int blk  = blockIdx.x % CTAS_PER_BATCH;

    // ---- staging ----
    if (tid < NF)
        s_yw[tid] = make_float4(TWO_PI_F * y_w[tid * 3],
                                TWO_PI_F * y_w[tid * 3 + 1],
                                TWO_PI_F * y_w[tid * 3 + 2],
                                TWO_PI_F * y_b[tid]);
    {
        const float* yg = y + ((size_t)bIdx * NGRID + (size_t)blk * PTS_PER_CTA) * 3;
        float* sp = (float*)s_pts;
        #pragma unroll
        for (int it = 0; it < 4; it++) {
            int j = tid + it * TPB;
            int pt = j >> 2, c = j & 3;
            sp[j] = (c < 3) ? yg[pt * 3 + c] : 0.0f;
        }
    }
    #pragma unroll
    for (int it = 0; it < 2; it++)
        s_G[tid + it * TPB] = g_G[bIdx * (64 * COUT) + tid + it * TPB];
    if (tid < COUT) s_ub[tid] = u_b[tid];
    __syncthreads();

    // ---- per-warp: M=32 rows x K=128 x N=8 ----
    const int warp = tid >> 5;
    const int lane = tid & 31;
    const int g = lane >> 2;
    const int t = lane & 3;
    const int base = warp * 32;

    float4 q0 = s_pts[base + g];
    float4 q1 = s_pts[base + g + 8];
    float4 q2 = s_pts[base + g + 16];
    float4 q3 = s_pts[base + g + 24];
    const float3 p0 = make_float3(q0.x, q0.y, q0.z);
    const float3 p1 = make_float3(q1.x, q1.y, q1.z);
    const float3 p2 = make_float3(q2.x, q2.y, q2.z);
    const float3 p3 = make_float3(q3.x, q3.y, q3.z);

    const float ub0 = s_ub[2 * t], ub1 = s_ub[2 * t + 1];
    float acc0[4] = {ub0, ub1, ub0, ub1};   // rows base+g, base+g+8
    float acc1[4] = {ub0, ub1, ub0, ub1};   // rows base+g+16, base+g+24

    #pragma unroll
    for (int kt = 0; kt < 8; kt++) {
        const int c0 = kt * 16 + 2 * t;
        float4 w0 = s_yw[c0], w1 = s_yw[c0 + 1], w2 = s_yw[c0 + 8], w3 = s_yw[c0 + 9];
        uint32_t a0 = pack_bf16x2(cosv(w0, p0), cosv(w1, p0));
        uint32_t a1 = pack_bf16x2(cosv(w0, p1), cosv(w1, p1));
        uint32_t a2 = pack_bf16x2(cosv(w2, p0), cosv(w3, p0));
        uint32_t a3 = pack_bf16x2(cosv(w2, p1), cosv(w3, p1));
        uint32_t a4 = pack_bf16x2(cosv(w0, p2), cosv(w1, p2));
        uint32_t a5 = pack_bf16x2(cosv(w0, p3), cosv(w1, p3));
        uint32_t a6 = pack_bf16x2(cosv(w2, p2), cosv(w3, p2));
        uint32_t a7 = pack_bf16x2(cosv(w2, p3), cosv(w3, p3));

        // B frag: G words at f-pair rows kt*8+t (b0) and kt*8+t+4 (b1), col o=g
        uint32_t b0 = s_G[(kt * 8 + t) * 8 + g];
        uint32_t b1 = s_G[(kt * 8 + t + 4) * 8 + g];
        mma16816(acc0, a0, a1, a2, a3, b0, b1);
        mma16816(acc1, a4, a5, a6, a7, b0, b1);
    }

    const size_t pt = (size_t)bIdx * NGRID + (size_t)blk * PTS_PER_CTA + base + g;
    *(float2*)(out + (pt +  0) * COUT + 2 * t) = make_float2(acc0[0], acc0[1]);
    *(float2*)(out + (pt +  8) * COUT + 2 * t) = make_float2(acc0[2], acc0[3]);
    *(float2*)(out + (pt + 16) * COUT + 2 * t) = make_float2(acc1[0], acc1[1]);
    *(float2*)(out + (pt + 24) * COUT + 2 * t) = make_float2(acc1[2], acc1[3]);
}

extern "C" void kernel_launch(void* const* d_in, const int* in_sizes, int n_in,
                              void* d_out, int out_size) {
    const float* h   = (const float*)d_in[0];
    const float* y   = (const float*)d_in[1];
    const float* y_w = (const float*)d_in[2];
    const float* y_b = (const float*)d_in[3];
    const float* u_w = (const float*)d_in[4];
    const float* u_b = (const float*)d_in[5];
    float* out = (float*)d_out;

    precompute_G_kernel<<<(BATCH * 64 * COUT) / TPB, TPB>>>(h, u_w);   // 8 blocks
    dim3 grid(BATCH * CTAS_PER_BATCH);                                  // 1728 CTAs
    spectral_hmma4_kernel<<<grid, TPB>>>(y, y_w, y_b, u_b, out);
}

// round 7
// speedup vs baseline: 1.4974x; 1.0906x over previous
#include <cuda_runtime.h>
#include <cuda_bf16.h>
#include <cstdint>

// SpectralInverse, linearized tail:
//   sin(x) ~ x at |x|<4e-4  =>  out[p,o] = u_b[o] + sum_f cos(2pi*Y[p,f]) * G[f,o]
//   with G = h . u_w^T / Ngrid  (precomputed, bf16 pairs, warp-per-word reduction)
// Main kernel: per-warp M=16 x K=128 x N=8 bf16 HMMA, cos generated straight into A-frags.
// TPB=512, launch_bounds(512,2) -> 64-reg clamp -> 32 warps/SM.

#define BATCH 4
#define NF 128
#define CIN 64
#define COUT 8
#define NGRID (48*48*48)
#define TPB 512
#define PTS_PER_CTA 256
#define CTAS_PER_BATCH (NGRID / PTS_PER_CTA)   // 432
#define TWO_PI_F 6.28318530717958647692f

// G as bf16x2 words: [batch][f/2][o] -> 4*64*8 = 2048 words
__device__ uint32_t g_G[BATCH * 64 * COUT];

__device__ __forceinline__ uint32_t pack_bf16x2(float lo, float hi) {
    uint32_t r;
    asm("cvt.rn.bf16x2.f32 %0, %1, %2;" : "=r"(r) : "f"(hi), "f"(lo));
    return r;  // r[15:0]=bf16(lo), r[31:16]=bf16(hi)
}

__device__ __forceinline__ void mma16816(float* d,
                                          uint32_t a0, uint32_t a1, uint32_t a2, uint32_t a3,
                                          uint32_t b0, uint32_t b1) {
    asm volatile("mma.sync.aligned.m16n8k16.row.col.f32.bf16.bf16.f32 "
                 "{%0,%1,%2,%3}, {%4,%5,%6,%7}, {%8,%9}, {%0,%1,%2,%3};"
                 : "+f"(d[0]), "+f"(d[1]), "+f"(d[2]), "+f"(d[3])
                 : "r"(a0), "r"(a1), "r"(a2), "r"(a3), "r"(b0), "r"(b1));
}

// w pre-scaled by 2*pi; __cosf handles range reduction.
__device__ __forceinline__ float cosv(float4 w, float3 p) {
    return __cosf(fmaf(w.x, p.x, fmaf(w.y, p.y, fmaf(w.z, p.z, w.w))));
}

// ---------------- kernel 1: G = h . u_w^T / N  — one warp per G word ----------------
__global__ void __launch_bounds__(256)
precompute_G_kernel(const float* __restrict__ h, const float* __restrict__ u_w)
{
    const int w    = blockIdx.x * 8 + (threadIdx.x >> 5);   // word id 0..2047
    const int lane = threadIdx.x & 31;
    const int b  = w >> 9;
    const int fp = (w >> 3) & 63;
    const int o  = w & 7;

    const float2* h0 = (const float2*)(h + ((size_t)b * NF + 2 * fp) * CIN);
    const float2* h1 = (const float2*)(h + ((size_t)b * NF + 2 * fp + 1) * CIN);
    const float2* uw = (const float2*)(u_w + o * CIN);

    float2 u  = uw[lane];
    float2 a0 = h0[lane];
    float2 a1 = h1[lane];
    float g0 = fmaf(a0.x, u.x, a0.y * u.y);
    float g1 = fmaf(a1.x, u.x, a1.y * u.y);
    #pragma unroll
    for (int off = 16; off > 0; off >>= 1) {
        g0 += __shfl_xor_sync(0xFFFFFFFFu, g0, off);
        g1 += __shfl_xor_sync(0xFFFFFFFFu, g1, off);
    }
    if (lane == 0) {
        const float inv_n = 1.0f / (float)NGRID;
        g_G[w] = pack_bf16x2(g0 * inv_n, g1 * inv_n);
    }
}

// ---------------- kernel 2: main ----------------
__global__ void __launch_bounds__(TPB, 2)
spectral_hmma5_kernel(const float* __restrict__ y,
                      const float* __restrict__ y_w,
                      const float* __restrict__ y_b,
                      const float* __restrict__ u_b,
                      float* __restrict__ out)
{
    __shared__ float4   s_pts[PTS_PER_CTA];   // 4096 B
    __shared__ float4   s_yw[NF];             // 2048 B (2pi-scaled w0,w1,w2,b)
    __shared__ uint32_t s_G[64 * COUT];       // 2048 B
    __shared__ float    s_ub[COUT];

    const int tid  = threadIdx.x;
    const int bIdx = blockIdx.x / CTAS_PER_BATCH;
    const int blk  = blockIdx.x % CTAS_PER_BATCH;

    // ---- staging ----
    if (tid < NF)
        s_yw[tid] = make_float4(TWO_PI_F * y_w[tid * 3],
                                TWO_PI_F * y_w[tid * 3 + 1],
                                TWO_PI_F * y_w[tid * 3 + 2],
                                TWO_PI_F * y_b[tid]);
    {
        const float* yg = y + ((size_t)bIdx * NGRID + (size_t)blk * PTS_PER_CTA) * 3;
        float* sp = (float*)s_pts;
        #pragma unroll
        for (int it = 0; it < 2; it++) {
            int j = tid + it * TPB;
            int pt = j >> 2, c = j & 3;
            sp[j] = (c < 3) ? yg[pt * 3 + c] : 0.0f;
        }
    }
    s_G[tid & 511] = g_G[bIdx * (64 * COUT) + (tid & 511)];
    if (tid < COUT) s_ub[tid] = u_b[tid];
    __syncthreads();

    // ---- per-warp: M=16 rows x K=128 x N=8 ----
    const int warp = tid >> 5;
    const int lane = tid & 31;
    const int g = lane >> 2;
    const int t = lane & 3;
    const int base = warp * 16;

    float4 q0 = s_pts[base + g];
    float4 q1 = s_pts[base + g + 8];
    const float3 p0 = make_float3(q0.x, q0.y, q0.z);
    const float3 p1 = make_float3(q1.x, q1.y, q1.z);

    const float ub0 = s_ub[2 * t], ub1 = s_ub[2 * t + 1];
    float acc[4] = {ub0, ub1, ub0, ub1};   // rows base+g (d0,d1), base+g+8 (d2,d3)

    #pragma unroll
    for (int kt = 0; kt < 8; kt++) {
        const int c0 = kt * 16 + 2 * t;
        float4 w0 = s_yw[c0], w1 = s_yw[c0 + 1], w2 = s_yw[c0 + 8], w3 = s_yw[c0 + 9];
        uint32_t a0 = pack_bf16x2(cosv(w0, p0), cosv(w1, p0));
        uint32_t a1 = pack_bf16x2(cosv(w0, p1), cosv(w1, p1));
        uint32_t a2 = pack_bf16x2(cosv(w2, p0), cosv(w3, p0));
        uint32_t a3 = pack_bf16x2(cosv(w2, p1), cosv(w3, p1));

        uint32_t b0 = s_G[(kt * 8 + t) * 8 + g];
        uint32_t b1 = s_G[(kt * 8 + t + 4) * 8 + g];
        mma16816(acc, a0, a1, a2, a3, b0, b1);
    }

    const size_t pt = (size_t)bIdx * NGRID + (size_t)blk * PTS_PER_CTA + base + g;
    *(float2*)(out + (pt + 0) * COUT + 2 * t) = make_float2(acc[0], acc[1]);
    *(float2*)(out + (pt + 8) * COUT + 2 * t) = make_float2(acc[2], acc[3]);
}

extern "C" void kernel_launch(void* const* d_in, const int* in_sizes, int n_in,
                              void* d_out, int out_size) {
    const float* h   = (const float*)d_in[0];
    const float* y   = (const float*)d_in[1];
    const float* y_w = (const float*)d_in[2];
    const float* y_b = (const float*)d_in[3];
    const float* u_w = (const float*)d_in[4];
    const float* u_b = (const float*)d_in[5];
    float* out = (float*)d_out;

    precompute_G_kernel<<<256, 256>>>(h, u_w);        // 2048 warps, warp-per-word
    dim3 grid(BATCH * CTAS_PER_BATCH);                 // 1728 CTAs
    spectral_hmma5_kernel<<<grid, TPB>>>(y, y_w, y_b, u_b, out);
}

// round 8
// speedup vs baseline: 1.6149x; 1.0784x over previous
#include <cuda_runtime.h>
#include <cuda_bf16.h>
#include <cstdint>

// SpectralInverse, linearized tail:
//   sin(x) ~ x at |x|<4e-4  =>  out[p,o] = u_b[o] + sum_f cos(2pi*Y[p,f]) * G[f,o]
//   with G = h . u_w^T / Ngrid  (precomputed, bf16 pairs, warp-per-word reduction)
// Main: per-warp M=32 x K=128 x N=8 bf16 HMMA, cos straight into A-frags.
// TPB=256, launch_bounds(256,4) -> 64-reg clamp -> 32 warps/SM target.

#define BATCH 4
#define NF 128
#define CIN 64
#define COUT 8
#define NGRID (48*48*48)
#define TPB 256
#define PTS_PER_CTA 256
#define CTAS_PER_BATCH (NGRID / PTS_PER_CTA)   // 432
#define TWO_PI_F 6.28318530717958647692f

// G as bf16x2 words: [batch][f/2][o] -> 4*64*8 = 2048 words
__device__ uint32_t g_G[BATCH * 64 * COUT];

__device__ __forceinline__ uint32_t pack_bf16x2(float lo, float hi) {
    uint32_t r;
    asm("cvt.rn.bf16x2.f32 %0, %1, %2;" : "=r"(r) : "f"(hi), "f"(lo));
    return r;  // r[15:0]=bf16(lo), r[31:16]=bf16(hi)
}

__device__ __forceinline__ void mma16816(float* d,
                                          uint32_t a0, uint32_t a1, uint32_t a2, uint32_t a3,
                                          uint32_t b0, uint32_t b1) {
    asm volatile("mma.sync.aligned.m16n8k16.row.col.f32.bf16.bf16.f32 "
                 "{%0,%1,%2,%3}, {%4,%5,%6,%7}, {%8,%9}, {%0,%1,%2,%3};"
                 : "+f"(d[0]), "+f"(d[1]), "+f"(d[2]), "+f"(d[3])
                 : "r"(a0), "r"(a1), "r"(a2), "r"(a3), "r"(b0), "r"(b1));
}

// w pre-scaled by 2*pi; __cosf handles range reduction.
__device__ __forceinline__ float cosv(float4 w, float3 p) {
    return __cosf(fmaf(w.x, p.x, fmaf(w.y, p.y, fmaf(w.z, p.z, w.w))));
}

// ---------------- kernel 1: G = h . u_w^T / N  — one warp per G word ----------------
__global__ void __launch_bounds__(256)
precompute_G_kernel(const float* __restrict__ h, const float* __restrict__ u_w)
{
    const int w    = blockIdx.x * 8 + (threadIdx.x >> 5);   // word id 0..2047
    const int lane = threadIdx.x & 31;
    const int b  = w >> 9;
    const int fp = (w >> 3) & 63;
    const int o  = w & 7;

    const float2* h0 = (const float2*)(h + ((size_t)b * NF + 2 * fp) * CIN);
    const float2* h1 = (const float2*)(h + ((size_t)b * NF + 2 * fp + 1) * CIN);
    const float2* uw = (const float2*)(u_w + o * CIN);

    float2 u  = uw[lane];
    float2 a0 = h0[lane];
    float2 a1 = h1[lane];
    float g0 = fmaf(a0.x, u.x, a0.y * u.y);
    float g1 = fmaf(a1.x, u.x, a1.y * u.y);
    #pragma unroll
    for (int off = 16; off > 0; off >>= 1) {
        g0 += __shfl_xor_sync(0xFFFFFFFFu, g0, off);
        g1 += __shfl_xor_sync(0xFFFFFFFFu, g1, off);
    }
    if (lane == 0) {
        const float inv_n = 1.0f / (float)NGRID;
        g_G[w] = pack_bf16x2(g0 * inv_n, g1 * inv_n);
    }
}

// ---------------- kernel 2: main ----------------
__global__ void __launch_bounds__(TPB, 4)
spectral_hmma6_kernel(const float* __restrict__ y,
                      const float* __restrict__ y_w,
                      const float* __restrict__ y_b,
                      const float* __restrict__ u_b,
                      float* __restrict__ out)
{
    __shared__ float4   s_pts[PTS_PER_CTA];   // 4096 B
    __shared__ float4   s_yw[NF];             // 2048 B (2pi-scaled w0,w1,w2,b)
    __shared__ uint32_t s_G[64 * COUT];       // 2048 B
    __shared__ float    s_ub[COUT];

    const int tid  = threadIdx.x;
    const int bIdx = blockIdx.x / CTAS_PER_BATCH;
    const int blk  = blockIdx.x % CTAS_PER_BATCH;

    // ---- staging ----
    if (tid < NF)
        s_yw[tid] = make_float4(TWO_PI_F * y_w[tid * 3],
                                TWO_PI_F * y_w[tid * 3 + 1],
                                TWO_PI_F * y_w[tid * 3 + 2],
                                TWO_PI_F * y_b[tid]);
    {
        const float* yg = y + ((size_t)bIdx * NGRID + (size_t)blk * PTS_PER_CTA) * 3;
        float* sp = (float*)s_pts;
        #pragma unroll
        for (int it = 0; it < 4; it++) {
            int j = tid + it * TPB;
            int pt = j >> 2, c = j & 3;
            sp[j] = (c < 3) ? yg[pt * 3 + c] : 0.0f;
        }
    }
    #pragma unroll
    for (int it = 0; it < 2; it++)
        s_G[tid + it * TPB] = g_G[bIdx * (64 * COUT) + tid + it * TPB];
    if (tid < COUT) s_ub[tid] = u_b[tid];
    __syncthreads();

    // ---- per-warp: M=32 rows x K=128 x N=8 ----
    const int warp = tid >> 5;
    const int lane = tid & 31;
    const int g = lane >> 2;
    const int t = lane & 3;
    const int base = warp * 32;

    float4 q0 = s_pts[base + g];
    float4 q1 = s_pts[base + g + 8];
    float4 q2 = s_pts[base + g + 16];
    float4 q3 = s_pts[base + g + 24];
    const float3 p0 = make_float3(q0.x, q0.y, q0.z);
    const float3 p1 = make_float3(q1.x, q1.y, q1.z);
    const float3 p2 = make_float3(q2.x, q2.y, q2.z);
    const float3 p3 = make_float3(q3.x, q3.y, q3.z);

    const float ub0 = s_ub[2 * t], ub1 = s_ub[2 * t + 1];
    float acc0[4] = {ub0, ub1, ub0, ub1};   // rows base+g, base+g+8
    float acc1[4] = {ub0, ub1, ub0, ub1};   // rows base+g+16, base+g+24

    #pragma unroll
    for (int kt = 0; kt < 8; kt++) {
        const int c0 = kt * 16 + 2 * t;
        float4 w0 = s_yw[c0], w1 = s_yw[c0 + 1], w2 = s_yw[c0 + 8], w3 = s_yw[c0 + 9];
        uint32_t a0 = pack_bf16x2(cosv(w0, p0), cosv(w1, p0));
        uint32_t a1 = pack_bf16x2(cosv(w0, p1), cosv(w1, p1));
        uint32_t a2 = pack_bf16x2(cosv(w2, p0), cosv(w3, p0));
        uint32_t a3 = pack_bf16x2(cosv(w2, p1), cosv(w3, p1));
        uint32_t a4 = pack_bf16x2(cosv(w0, p2), cosv(w1, p2));
        uint32_t a5 = pack_bf16x2(cosv(w0, p3), cosv(w1, p3));
        uint32_t a6 = pack_bf16x2(cosv(w2, p2), cosv(w3, p2));
        uint32_t a7 = pack_bf16x2(cosv(w2, p3), cosv(w3, p3));

        uint32_t b0 = s_G[(kt * 8 + t) * 8 + g];
        uint32_t b1 = s_G[(kt * 8 + t + 4) * 8 + g];
        mma16816(acc0, a0, a1, a2, a3, b0, b1);
        mma16816(acc1, a4, a5, a6, a7, b0, b1);
    }

    const size_t pt = (size_t)bIdx * NGRID + (size_t)blk * PTS_PER_CTA + base + g;
    *(float2*)(out + (pt +  0) * COUT + 2 * t) = make_float2(acc0[0], acc0[1]);
    *(float2*)(out + (pt +  8) * COUT + 2 * t) = make_float2(acc0[2], acc0[3]);
    *(float2*)(out + (pt + 16) * COUT + 2 * t) = make_float2(acc1[0], acc1[1]);
    *(float2*)(out + (pt + 24) * COUT + 2 * t) = make_float2(acc1[2], acc1[3]);
}

extern "C" void kernel_launch(void* const* d_in, const int* in_sizes, int n_in,
                              void* d_out, int out_size) {
    const float* h   = (const float*)d_in[0];
    const float* y   = (const float*)d_in[1];
    const float* y_w = (const float*)d_in[2];
    const float* y_b = (const float*)d_in[3];
    const float* u_w = (const float*)d_in[4];
    const float* u_b = (const float*)d_in[5];
    float* out = (float*)d_out;

    precompute_G_kernel<<<256, 256>>>(h, u_w);        // 2048 warps, warp-per-word
    dim3 grid(BATCH * CTAS_PER_BATCH);                 // 1728 CTAs
    spectral_hmma6_kernel<<<grid, TPB>>>(y, y_w, y_b, u_b, out);
}